// round 5
// baseline (speedup 1.0000x reference)
#include <cuda_runtime.h>
#include <cuda_bf16.h>
#include <math.h>

// ---------------------------------------------------------------------------
// Problem constants
// ---------------------------------------------------------------------------
#define NN   50000
#define EE   400000
#define ETOT (EE + NN)
#define GG   256
#define FMAX 256
#define SCAN_BLK 1024
#define SCAN_NB  ((NN + SCAN_BLK - 1) / SCAN_BLK)   // 49

// ---------------------------------------------------------------------------
// Scratch
// ---------------------------------------------------------------------------
__device__ float g_xl[(size_t)NN * FMAX];
__device__ float g_xr[(size_t)NN * FMAX];
__device__ float g_h [(size_t)NN * FMAX];
__device__ int   g_deg [NN];
__device__ int   g_row [NN + 1];
__device__ int   g_fill[NN];
__device__ int   g_col [ETOT];
__device__ int   g_bsum[SCAN_NB];

__device__ __forceinline__ float to_tf32(float x) {
    float r;
    asm("cvt.rna.tf32.f32 %0, %1;" : "=f"(r) : "f"(x));
    return r;
}

// ---------------------------------------------------------------------------
// CSR build. Self-loops are implicit: every node gets +1 degree and its
// self-loop occupies slot row[i] (written by scan_apply); real edges fill
// slots row[i]+1 .. row[i+1)-1 via atomic fill counters.
// ---------------------------------------------------------------------------
__global__ void init_kernel(int4* deg4) {
    int i = blockIdx.x * blockDim.x + threadIdx.x;
    if (i < NN / 4) deg4[i] = make_int4(0, 0, 0, 0);
}

__global__ void hist_kernel(const int* __restrict__ edge_index, int* deg) {
    int t = blockIdx.x * blockDim.x + threadIdx.x;
    if (t >= EE / 4) return;
    int4 d = ((const int4*)(edge_index + EE))[t];
    atomicAdd(&deg[d.x], 1);
    atomicAdd(&deg[d.y], 1);
    atomicAdd(&deg[d.z], 1);
    atomicAdd(&deg[d.w], 1);
}

// Stage 1: per-block inclusive scan of (deg+1) -> row[i+1] (block-local), total -> bsum
__global__ __launch_bounds__(SCAN_BLK) void scan_partial(
    const int* __restrict__ deg, int* __restrict__ row, int* __restrict__ bsum) {
    __shared__ int wsum[32];
    int tid = threadIdx.x, lane = tid & 31, wid = tid >> 5;
    int i = blockIdx.x * SCAN_BLK + tid;
    int v = (i < NN) ? deg[i] + 1 : 0;
    int x = v;
    #pragma unroll
    for (int o = 1; o < 32; o <<= 1) {
        int t = __shfl_up_sync(0xffffffffu, x, o);
        if (lane >= o) x += t;
    }
    if (lane == 31) wsum[wid] = x;
    __syncthreads();
    if (wid == 0) {
        int s = wsum[lane];
        #pragma unroll
        for (int o = 1; o < 32; o <<= 1) {
            int t = __shfl_up_sync(0xffffffffu, s, o);
            if (lane >= o) s += t;
        }
        wsum[lane] = s;
    }
    __syncthreads();
    int incl = x + (wid > 0 ? wsum[wid - 1] : 0);
    if (i < NN) row[i + 1] = incl;
    if (tid == SCAN_BLK - 1) bsum[blockIdx.x] = incl;
}

// Stage 2: add block prefix (computed in-block from the 49 bsums), emit
// self-loop entry + fill pointer.
__global__ __launch_bounds__(SCAN_BLK) void scan_apply(
    const int* __restrict__ deg, int* __restrict__ row,
    int* __restrict__ fill, const int* __restrict__ bsum,
    int* __restrict__ col) {
    __shared__ int soff;
    int tid = threadIdx.x, lane = tid & 31;
    int bid = blockIdx.x;
    if (tid < 32) {
        int acc = 0;
        for (int b = lane; b < bid; b += 32) acc += bsum[b];
        #pragma unroll
        for (int o = 16; o > 0; o >>= 1)
            acc += __shfl_xor_sync(0xffffffffu, acc, o);
        if (lane == 0) soff = acc;
    }
    __syncthreads();
    int i = bid * SCAN_BLK + tid;
    if (i >= NN) return;
    int incl = row[i + 1] + soff;
    row[i + 1] = incl;
    int excl = incl - (deg[i] + 1);
    col[excl] = i;           // self loop in slot 0 of this row
    fill[i] = excl + 1;
    if (i == 0) row[0] = 0;
}

__global__ void scatter_kernel(const int* __restrict__ edge_index,
                               int* fill, int* __restrict__ col) {
    int t = blockIdx.x * blockDim.x + threadIdx.x;
    if (t >= EE / 4) return;
    int4 s = ((const int4*)edge_index)[t];
    int4 d = ((const int4*)(edge_index + EE))[t];
    int p0 = atomicAdd(&fill[d.x], 1); col[p0] = s.x;
    int p1 = atomicAdd(&fill[d.y], 1); col[p1] = s.y;
    int p2 = atomicAdd(&fill[d.z], 1); col[p2] = s.z;
    int p3 = atomicAdd(&fill[d.w], 1); col[p3] = s.w;
}

// ---------------------------------------------------------------------------
// TF32 GEMM, fused l/r (blockIdx.z). C[N,M] = A[N,K] * W[M,K]^T.
// BM=128, BN=128, BK=32, 512 threads. Double-buffered smem (dynamic, 72KB),
// one __syncthreads per k-iter, ldmatrix.x4 fragment loads.
// Smem row stride 36 floats -> ldmatrix rows hit banks 4r+k: conflict-free.
// ---------------------------------------------------------------------------
#define GEMM_SMEM (2 * 2 * 128 * 36 * 4)   // 73728 bytes
#define STG_F     (128 * 36)               // floats per tile per stage

__device__ __forceinline__ void ldsm_x4(unsigned addr, unsigned& r0, unsigned& r1,
                                        unsigned& r2, unsigned& r3) {
    asm volatile("ldmatrix.sync.aligned.m8n8.x4.shared.b16 {%0,%1,%2,%3}, [%4];"
                 : "=r"(r0), "=r"(r1), "=r"(r2), "=r"(r3) : "r"(addr));
}

__global__ __launch_bounds__(512) void tf32_gemm2(const float* __restrict__ A,
                                                  const float* __restrict__ Wl,
                                                  const float* __restrict__ Wr,
                                                  float* __restrict__ Cl,
                                                  float* __restrict__ Cr,
                                                  int Nrows, int K, int M) {
    extern __shared__ float smem[];
    float* AsBase = smem;                 // [2][128*36]
    float* BsBase = smem + 2 * STG_F;     // [2][128*36]

    const float* W = blockIdx.z ? Wr : Wl;
    float*       C = blockIdx.z ? Cr : Cl;

    int tid = threadIdx.x;
    int lane = tid & 31, wid = tid >> 5;
    int warpM = wid & 3, warpN = wid >> 2;
    int quad = lane >> 2, tq = lane & 3;
    int rowBase = blockIdx.y * 128;
    int colBase = blockIdx.x * 128;

    // ldmatrix per-lane addressing offsets
    int lmRow = (((lane >> 3) & 1) << 3) + (lane & 7);  // 0..15
    int lmK   = ((lane >> 4) << 2);                      // 0 or 4

    // global loader indices
    int ldRow = tid >> 3;          // 0..63 (tid), +64 with second chunk
    int ldKq  = (tid & 7) * 4;

    float acc[2][4][4];
    #pragma unroll
    for (int mi = 0; mi < 2; mi++)
        #pragma unroll
        for (int ni = 0; ni < 4; ni++)
            #pragma unroll
            for (int r = 0; r < 4; r++) acc[mi][ni][r] = 0.0f;

    float4 aReg[2], bReg[2];
    auto load_regs = [&](int k0) {
        #pragma unroll
        for (int i = 0; i < 2; i++) {
            int r = ldRow + 64 * i;
            int gr = rowBase + r;
            float4 v = make_float4(0.f, 0.f, 0.f, 0.f);
            if (gr < Nrows) v = *(const float4*)&A[(size_t)gr * K + k0 + ldKq];
            aReg[i].x = to_tf32(v.x); aReg[i].y = to_tf32(v.y);
            aReg[i].z = to_tf32(v.z); aReg[i].w = to_tf32(v.w);
            int gbr = colBase + r;
            float4 w = make_float4(0.f, 0.f, 0.f, 0.f);
            if (gbr < M) w = *(const float4*)&W[(size_t)gbr * K + k0 + ldKq];
            bReg[i].x = to_tf32(w.x); bReg[i].y = to_tf32(w.y);
            bReg[i].z = to_tf32(w.z); bReg[i].w = to_tf32(w.w);
        }
    };
    auto store_smem = [&](int s) {
        float* As = AsBase + s * STG_F;
        float* Bs = BsBase + s * STG_F;
        #pragma unroll
        for (int i = 0; i < 2; i++) {
            int r = ldRow + 64 * i;
            *(float4*)&As[r * 36 + ldKq] = aReg[i];
            *(float4*)&Bs[r * 36 + ldKq] = bReg[i];
        }
    };

    int nIter = K >> 5;
    load_regs(0);
    store_smem(0);
    __syncthreads();

    for (int it = 0; it < nIter; it++) {
        int cur = it & 1;
        if (it + 1 < nIter) load_regs((it + 1) << 5);

        unsigned asu = (unsigned)__cvta_generic_to_shared(AsBase + cur * STG_F);
        unsigned bsu = (unsigned)__cvta_generic_to_shared(BsBase + cur * STG_F);
        #pragma unroll
        for (int ks = 0; ks < 4; ks++) {
            int kk = ks * 8;
            unsigned a0[4], a1[4], b0[4], b1[4];
            ldsm_x4(asu + ((warpM * 32 +      lmRow) * 36 + kk + lmK) * 4,
                    a0[0], a0[1], a0[2], a0[3]);
            ldsm_x4(asu + ((warpM * 32 + 16 + lmRow) * 36 + kk + lmK) * 4,
                    a1[0], a1[1], a1[2], a1[3]);
            ldsm_x4(bsu + ((warpN * 32 +      lmRow) * 36 + kk + lmK) * 4,
                    b0[0], b0[1], b0[2], b0[3]);
            ldsm_x4(bsu + ((warpN * 32 + 16 + lmRow) * 36 + kk + lmK) * 4,
                    b1[0], b1[1], b1[2], b1[3]);
            // b0 = {B[ni0].k0, B[ni1].k0, B[ni0].k1, B[ni1].k1}; b1 likewise ni2/ni3
            unsigned* aa[2] = {a0, a1};
            unsigned bb[4][2] = {{b0[0], b0[2]}, {b0[1], b0[3]},
                                 {b1[0], b1[2]}, {b1[1], b1[3]}};
            #pragma unroll
            for (int mi = 0; mi < 2; mi++)
                #pragma unroll
                for (int ni = 0; ni < 4; ni++) {
                    asm volatile(
                        "mma.sync.aligned.m16n8k8.row.col.f32.tf32.tf32.f32 "
                        "{%0,%1,%2,%3},{%4,%5,%6,%7},{%8,%9},{%0,%1,%2,%3};"
                        : "+f"(acc[mi][ni][0]), "+f"(acc[mi][ni][1]),
                          "+f"(acc[mi][ni][2]), "+f"(acc[mi][ni][3])
                        : "r"(aa[mi][0]), "r"(aa[mi][1]), "r"(aa[mi][2]), "r"(aa[mi][3]),
                          "r"(bb[ni][0]), "r"(bb[ni][1]));
                }
        }
        if (it + 1 < nIter) store_smem(1 - cur);
        __syncthreads();
    }

    #pragma unroll
    for (int mi = 0; mi < 2; mi++) {
        #pragma unroll
        for (int half = 0; half < 2; half++) {
            int r = rowBase + warpM * 32 + mi * 16 + quad + half * 8;
            if (r >= Nrows) continue;
            #pragma unroll
            for (int ni = 0; ni < 4; ni++) {
                int c = colBase + warpN * 32 + ni * 8 + 2 * tq;
                if (c >= M) continue;
                float2 v;
                v.x = acc[mi][ni][half * 2 + 0];
                v.y = acc[mi][ni][half * 2 + 1];
                *(float2*)&C[(size_t)r * M + c] = v;
            }
        }
    }
}

// ---------------------------------------------------------------------------
// GATv2 aggregation, warp per (node, 128-feature chunk), 4-edge unroll,
// NO running max (logits are O(10), exp cannot overflow fp32), two
// independent accumulator sets -> no serial recurrence.
// Lane owns features f = 128*chunk + 4*lane + [0,4); head spans 16 lanes.
// ---------------------------------------------------------------------------
__device__ __forceinline__ float dot_lrelu(float4 v, float4 xrr, float4 attr) {
    float zx = v.x + xrr.x; zx = zx > 0.f ? zx : 0.2f * zx;
    float zy = v.y + xrr.y; zy = zy > 0.f ? zy : 0.2f * zy;
    float zz = v.z + xrr.z; zz = zz > 0.f ? zz : 0.2f * zz;
    float zw = v.w + xrr.w; zw = zw > 0.f ? zw : 0.2f * zw;
    return attr.x * zx + attr.y * zy + attr.z * zz + attr.w * zw;
}

template <int F>
__global__ __launch_bounds__(256) void gat_agg_chunk_kernel(
    const float* __restrict__ xl, const float* __restrict__ xr,
    const int* __restrict__ rowptr, const int* __restrict__ colidx,
    const float* __restrict__ att, const float* __restrict__ bias,
    float* __restrict__ out) {
    constexpr int rowF4 = F / 4;
    int node = (blockIdx.x * blockDim.x + threadIdx.x) >> 5;
    int lane = threadIdx.x & 31;
    if (node >= NN) return;
    int fi = blockIdx.y * 32 + lane;

    const float4* xl4 = (const float4*)xl;
    float4 xrr  = ((const float4*)xr)[(size_t)node * rowF4 + fi];
    float4 attr = ((const float4*)att)[fi];

    float psumA = 0.f, psumB = 0.f;
    float4 accA = make_float4(0.f, 0.f, 0.f, 0.f);
    float4 accB = make_float4(0.f, 0.f, 0.f, 0.f);

    int beg = rowptr[node], end = rowptr[node + 1];
    int j = beg;
    for (; j + 4 <= end; j += 4) {
        int s0 = colidx[j], s1 = colidx[j + 1], s2 = colidx[j + 2], s3 = colidx[j + 3];
        float4 v0 = xl4[(size_t)s0 * rowF4 + fi];
        float4 v1 = xl4[(size_t)s1 * rowF4 + fi];
        float4 v2 = xl4[(size_t)s2 * rowF4 + fi];
        float4 v3 = xl4[(size_t)s3 * rowF4 + fi];
        float p0 = dot_lrelu(v0, xrr, attr);
        float p1 = dot_lrelu(v1, xrr, attr);
        float p2 = dot_lrelu(v2, xrr, attr);
        float p3 = dot_lrelu(v3, xrr, attr);
        #pragma unroll
        for (int o = 1; o < 16; o <<= 1) {
            p0 += __shfl_xor_sync(0xffffffffu, p0, o);
            p1 += __shfl_xor_sync(0xffffffffu, p1, o);
            p2 += __shfl_xor_sync(0xffffffffu, p2, o);
            p3 += __shfl_xor_sync(0xffffffffu, p3, o);
        }
        float e0 = __expf(p0), e1 = __expf(p1), e2 = __expf(p2), e3 = __expf(p3);
        psumA += e0 + e1;
        psumB += e2 + e3;
        accA.x += e0 * v0.x + e1 * v1.x;  accB.x += e2 * v2.x + e3 * v3.x;
        accA.y += e0 * v0.y + e1 * v1.y;  accB.y += e2 * v2.y + e3 * v3.y;
        accA.z += e0 * v0.z + e1 * v1.z;  accB.z += e2 * v2.z + e3 * v3.z;
        accA.w += e0 * v0.w + e1 * v1.w;  accB.w += e2 * v2.w + e3 * v3.w;
    }
    for (; j < end; j++) {
        int s0 = colidx[j];
        float4 v0 = xl4[(size_t)s0 * rowF4 + fi];
        float p0 = dot_lrelu(v0, xrr, attr);
        #pragma unroll
        for (int o = 1; o < 16; o <<= 1)
            p0 += __shfl_xor_sync(0xffffffffu, p0, o);
        float e0 = __expf(p0);
        psumA += e0;
        accA.x += e0 * v0.x; accA.y += e0 * v0.y;
        accA.z += e0 * v0.z; accA.w += e0 * v0.w;
    }

    float4 bi = ((const float4*)bias)[fi];
    float inv = 1.0f / (psumA + psumB + 1e-16f);
    float4 v;
    v.x = (accA.x + accB.x) * inv + bi.x;
    v.y = (accA.y + accB.y) * inv + bi.y;
    v.z = (accA.z + accB.z) * inv + bi.z;
    v.w = (accA.w + accB.w) * inv + bi.w;
    v.x = v.x > 0.f ? v.x : 0.01f * v.x;
    v.y = v.y > 0.f ? v.y : 0.01f * v.y;
    v.z = v.z > 0.f ? v.z : 0.01f * v.z;
    v.w = v.w > 0.f ? v.w : 0.01f * v.w;
    ((float4*)out)[(size_t)node * rowF4 + fi] = v;
}

// H = 1 (F = 64): float2 per lane, full-warp reduce, 4-edge unroll, no max.
__global__ __launch_bounds__(256) void gat_agg1_kernel(
    const float* __restrict__ xl, const float* __restrict__ xr,
    const int* __restrict__ rowptr, const int* __restrict__ colidx,
    const float* __restrict__ att, const float* __restrict__ bias,
    float* __restrict__ out) {
    int node = (blockIdx.x * blockDim.x + threadIdx.x) >> 5;
    int lane = threadIdx.x & 31;
    if (node >= NN) return;

    const float2* xl2 = (const float2*)xl;
    float2 xrr = ((const float2*)xr)[(size_t)node * 32 + lane];
    float2 attr = ((const float2*)att)[lane];

    float psumA = 0.f, psumB = 0.f;
    float2 accA = make_float2(0.f, 0.f), accB = make_float2(0.f, 0.f);

    auto dot2 = [&](float2 v) {
        float zx = v.x + xrr.x; zx = zx > 0.f ? zx : 0.2f * zx;
        float zy = v.y + xrr.y; zy = zy > 0.f ? zy : 0.2f * zy;
        return attr.x * zx + attr.y * zy;
    };

    int beg = rowptr[node], end = rowptr[node + 1];
    int j = beg;
    for (; j + 4 <= end; j += 4) {
        int s0 = colidx[j], s1 = colidx[j + 1], s2 = colidx[j + 2], s3 = colidx[j + 3];
        float2 v0 = xl2[(size_t)s0 * 32 + lane];
        float2 v1 = xl2[(size_t)s1 * 32 + lane];
        float2 v2 = xl2[(size_t)s2 * 32 + lane];
        float2 v3 = xl2[(size_t)s3 * 32 + lane];
        float p0 = dot2(v0), p1 = dot2(v1), p2 = dot2(v2), p3 = dot2(v3);
        #pragma unroll
        for (int o = 1; o < 32; o <<= 1) {
            p0 += __shfl_xor_sync(0xffffffffu, p0, o);
            p1 += __shfl_xor_sync(0xffffffffu, p1, o);
            p2 += __shfl_xor_sync(0xffffffffu, p2, o);
            p3 += __shfl_xor_sync(0xffffffffu, p3, o);
        }
        float e0 = __expf(p0), e1 = __expf(p1), e2 = __expf(p2), e3 = __expf(p3);
        psumA += e0 + e1;
        psumB += e2 + e3;
        accA.x += e0 * v0.x + e1 * v1.x;  accB.x += e2 * v2.x + e3 * v3.x;
        accA.y += e0 * v0.y + e1 * v1.y;  accB.y += e2 * v2.y + e3 * v3.y;
    }
    for (; j < end; j++) {
        int s0 = colidx[j];
        float2 v0 = xl2[(size_t)s0 * 32 + lane];
        float p0 = dot2(v0);
        #pragma unroll
        for (int o = 1; o < 32; o <<= 1)
            p0 += __shfl_xor_sync(0xffffffffu, p0, o);
        float e0 = __expf(p0);
        psumA += e0;
        accA.x += e0 * v0.x; accA.y += e0 * v0.y;
    }

    float2 bi = ((const float2*)bias)[lane];
    float inv = 1.0f / (psumA + psumB + 1e-16f);
    float2 v;
    v.x = (accA.x + accB.x) * inv + bi.x;
    v.y = (accA.y + accB.y) * inv + bi.y;
    v.x = v.x > 0.f ? v.x : 0.01f * v.x;
    v.y = v.y > 0.f ? v.y : 0.01f * v.y;
    ((float2*)out)[(size_t)node * 32 + lane] = v;
}

// ---------------------------------------------------------------------------
// Fused pooling + head (batch_index sorted -> binary-searched ranges)
// ---------------------------------------------------------------------------
__global__ __launch_bounds__(256) void pool_head_kernel(
    const float* __restrict__ h, const int* __restrict__ batch,
    const float* __restrict__ out_w, const float* __restrict__ out_b,
    float* __restrict__ d_out) {
    int g = blockIdx.x;
    int t = threadIdx.x;
    int f = t & 63, slice = t >> 6;

    __shared__ int bounds[2];
    __shared__ float smax[4][64], ssum[4][64];
    __shared__ float hid[128];

    if (t < 2) {
        int key = g + t;
        int lo = 0, hi = NN;
        while (lo < hi) {
            int mid = (lo + hi) >> 1;
            if (batch[mid] < key) lo = mid + 1; else hi = mid;
        }
        bounds[t] = lo;
    }
    __syncthreads();
    int start = bounds[0], end = bounds[1];

    float mx = -INFINITY, sm = 0.0f;
    for (int n = start + slice; n < end; n += 4) {
        float v = h[(size_t)n * 64 + f];
        mx = fmaxf(mx, v);
        sm += v;
    }
    smax[slice][f] = mx;
    ssum[slice][f] = sm;
    __syncthreads();

    if (t < 64) {
        float m = fmaxf(fmaxf(smax[0][t], smax[1][t]), fmaxf(smax[2][t], smax[3][t]));
        float s = ssum[0][t] + ssum[1][t] + ssum[2][t] + ssum[3][t];
        int cnt = end - start;
        float inv = 1.0f / (float)(cnt > 1 ? cnt : 1);
        hid[t] = m;
        hid[64 + t] = s * inv;
    }
    __syncthreads();

    if (t < 128) d_out[512 + (size_t)g * 128 + t] = hid[t];
    if (t < 2) {
        float s = out_b[t];
        #pragma unroll 8
        for (int k = 0; k < 128; k++) s = fmaf(hid[k], out_w[t * 128 + k], s);
        d_out[g * 2 + t] = s;
    }
}

// ---------------------------------------------------------------------------
// Launch
// ---------------------------------------------------------------------------
extern "C" void kernel_launch(void* const* d_in, const int* in_sizes, int n_in,
                              void* d_out, int out_size) {
    const float* x        = (const float*)d_in[0];
    const int*   edge_idx = (const int*)d_in[1];
    const int*   batch    = (const int*)d_in[2];
    const float* w1_l = (const float*)d_in[3];
    const float* w1_r = (const float*)d_in[4];
    const float* att1 = (const float*)d_in[5];
    const float* b1   = (const float*)d_in[6];
    const float* w2_l = (const float*)d_in[7];
    const float* w2_r = (const float*)d_in[8];
    const float* att2 = (const float*)d_in[9];
    const float* b2   = (const float*)d_in[10];
    const float* w3_l = (const float*)d_in[11];
    const float* w3_r = (const float*)d_in[12];
    const float* att3 = (const float*)d_in[13];
    const float* b3   = (const float*)d_in[14];
    const float* out_w = (const float*)d_in[15];
    const float* out_b = (const float*)d_in[16];
    float* out = (float*)d_out;

    void* p;
    float *xl, *xr, *h; int *deg, *row, *fill, *col, *bsum;
    cudaGetSymbolAddress(&p, g_xl);   xl   = (float*)p;
    cudaGetSymbolAddress(&p, g_xr);   xr   = (float*)p;
    cudaGetSymbolAddress(&p, g_h);    h    = (float*)p;
    cudaGetSymbolAddress(&p, g_deg);  deg  = (int*)p;
    cudaGetSymbolAddress(&p, g_row);  row  = (int*)p;
    cudaGetSymbolAddress(&p, g_fill); fill = (int*)p;
    cudaGetSymbolAddress(&p, g_col);  col  = (int*)p;
    cudaGetSymbolAddress(&p, g_bsum); bsum = (int*)p;

    cudaFuncSetAttribute(tf32_gemm2, cudaFuncAttributeMaxDynamicSharedMemorySize,
                         GEMM_SMEM);

    // --- CSR build ---
    init_kernel<<<(NN / 4 + 255) / 256, 256>>>((int4*)deg);
    hist_kernel<<<(EE / 4 + 255) / 256, 256>>>(edge_idx, deg);
    scan_partial<<<SCAN_NB, SCAN_BLK>>>(deg, row, bsum);
    scan_apply<<<SCAN_NB, SCAN_BLK>>>(deg, row, fill, bsum, col);
    scatter_kernel<<<(EE / 4 + 255) / 256, 256>>>(edge_idx, fill, col);

    const int AGG_BLOCKS = (NN * 32 + 255) / 256;
    const int NB = (NN + 127) / 128;

    // --- Layer 1: 128 -> 256 (H=4, 2 chunks) ---
    tf32_gemm2<<<dim3(2, NB, 2), 512, GEMM_SMEM>>>(x, w1_l, w1_r, xl, xr, NN, 128, 256);
    gat_agg_chunk_kernel<256><<<dim3(AGG_BLOCKS, 2), 256>>>(xl, xr, row, col, att1, b1, h);

    // --- Layer 2: 256 -> 128 (H=2, 1 chunk) ---
    tf32_gemm2<<<dim3(1, NB, 2), 512, GEMM_SMEM>>>(h, w2_l, w2_r, xl, xr, NN, 256, 128);
    gat_agg_chunk_kernel<128><<<dim3(AGG_BLOCKS, 1), 256>>>(xl, xr, row, col, att2, b2, h);

    // --- Layer 3: 128 -> 64 (H=1) ---
    tf32_gemm2<<<dim3(1, NB, 2), 512, GEMM_SMEM>>>(h, w3_l, w3_r, xl, xr, NN, 128, 64);
    gat_agg1_kernel<<<AGG_BLOCKS, 256>>>(xl, xr, row, col, att3, b3, h);

    // --- Fused pooling + head ---
    pool_head_kernel<<<GG, 256>>>(h, batch, out_w, out_b, out);
}

// round 6
// speedup vs baseline: 1.0926x; 1.0926x over previous
#include <cuda_runtime.h>
#include <cuda_bf16.h>
#include <math.h>

// ---------------------------------------------------------------------------
// Problem constants
// ---------------------------------------------------------------------------
#define NN   50000
#define EE   400000
#define ETOT (EE + NN)
#define GG   256
#define FMAX 256
#define SCAN_BLK 1024
#define SCAN_NB  ((NN + SCAN_BLK - 1) / SCAN_BLK)   // 49

// ---------------------------------------------------------------------------
// Scratch
// ---------------------------------------------------------------------------
__device__ float g_xl[(size_t)NN * FMAX];
__device__ float g_xr[(size_t)NN * FMAX];
__device__ float g_h [(size_t)NN * FMAX];
__device__ int   g_deg [NN];
__device__ int   g_row [NN + 1];
__device__ int   g_fill[NN];
__device__ int   g_col [ETOT];
__device__ int   g_bsum[SCAN_NB];

__device__ __forceinline__ float to_tf32(float x) {
    float r;
    asm("cvt.rna.tf32.f32 %0, %1;" : "=f"(r) : "f"(x));
    return r;
}

// ---------------------------------------------------------------------------
// CSR build. Self-loops implicit: node i gets +1 degree; slot row[i] holds i.
// ---------------------------------------------------------------------------
__global__ void init_kernel(int4* deg4) {
    int i = blockIdx.x * blockDim.x + threadIdx.x;
    if (i < NN / 4) deg4[i] = make_int4(0, 0, 0, 0);
}

__global__ void hist_kernel(const int* __restrict__ edge_index, int* deg) {
    int t = blockIdx.x * blockDim.x + threadIdx.x;
    if (t >= EE / 4) return;
    int4 d = ((const int4*)(edge_index + EE))[t];
    atomicAdd(&deg[d.x], 1);
    atomicAdd(&deg[d.y], 1);
    atomicAdd(&deg[d.z], 1);
    atomicAdd(&deg[d.w], 1);
}

__global__ __launch_bounds__(SCAN_BLK) void scan_partial(
    const int* __restrict__ deg, int* __restrict__ row, int* __restrict__ bsum) {
    __shared__ int wsum[32];
    int tid = threadIdx.x, lane = tid & 31, wid = tid >> 5;
    int i = blockIdx.x * SCAN_BLK + tid;
    int v = (i < NN) ? deg[i] + 1 : 0;
    int x = v;
    #pragma unroll
    for (int o = 1; o < 32; o <<= 1) {
        int t = __shfl_up_sync(0xffffffffu, x, o);
        if (lane >= o) x += t;
    }
    if (lane == 31) wsum[wid] = x;
    __syncthreads();
    if (wid == 0) {
        int s = wsum[lane];
        #pragma unroll
        for (int o = 1; o < 32; o <<= 1) {
            int t = __shfl_up_sync(0xffffffffu, s, o);
            if (lane >= o) s += t;
        }
        wsum[lane] = s;
    }
    __syncthreads();
    int incl = x + (wid > 0 ? wsum[wid - 1] : 0);
    if (i < NN) row[i + 1] = incl;
    if (tid == SCAN_BLK - 1) bsum[blockIdx.x] = incl;
}

__global__ __launch_bounds__(SCAN_BLK) void scan_apply(
    const int* __restrict__ deg, int* __restrict__ row,
    int* __restrict__ fill, const int* __restrict__ bsum,
    int* __restrict__ col) {
    __shared__ int soff;
    int tid = threadIdx.x, lane = tid & 31;
    int bid = blockIdx.x;
    if (tid < 32) {
        int acc = 0;
        for (int b = lane; b < bid; b += 32) acc += bsum[b];
        #pragma unroll
        for (int o = 16; o > 0; o >>= 1)
            acc += __shfl_xor_sync(0xffffffffu, acc, o);
        if (lane == 0) soff = acc;
    }
    __syncthreads();
    int i = bid * SCAN_BLK + tid;
    if (i >= NN) return;
    int incl = row[i + 1] + soff;
    row[i + 1] = incl;
    int excl = incl - (deg[i] + 1);
    col[excl] = i;           // self loop in slot 0
    fill[i] = excl + 1;
    if (i == 0) row[0] = 0;
}

__global__ void scatter_kernel(const int* __restrict__ edge_index,
                               int* fill, int* __restrict__ col) {
    int t = blockIdx.x * blockDim.x + threadIdx.x;
    if (t >= EE / 4) return;
    int4 s = ((const int4*)edge_index)[t];
    int4 d = ((const int4*)(edge_index + EE))[t];
    int p0 = atomicAdd(&fill[d.x], 1); col[p0] = s.x;
    int p1 = atomicAdd(&fill[d.y], 1); col[p1] = s.y;
    int p2 = atomicAdd(&fill[d.z], 1); col[p2] = s.z;
    int p3 = atomicAdd(&fill[d.w], 1); col[p3] = s.w;
}

// ---------------------------------------------------------------------------
// TF32 GEMM, fused l/r (blockIdx.z). C[N,M] = A[N,K] * W[M,K]^T.
// BM=128, BN=128, BK=32, 512 threads. (Round-4 proven version.)
// ---------------------------------------------------------------------------
__global__ __launch_bounds__(512) void tf32_gemm2(const float* __restrict__ A,
                                                  const float* __restrict__ Wl,
                                                  const float* __restrict__ Wr,
                                                  float* __restrict__ Cl,
                                                  float* __restrict__ Cr,
                                                  int Nrows, int K, int M) {
    __shared__ float As[128][36];
    __shared__ float Bs[128][36];

    const float* W = blockIdx.z ? Wr : Wl;
    float*       C = blockIdx.z ? Cr : Cl;

    int tid = threadIdx.x;
    int lane = tid & 31, wid = tid >> 5;
    int warpM = wid & 3, warpN = wid >> 2;
    int quad = lane >> 2, tq = lane & 3;
    int rowBase = blockIdx.y * 128;
    int colBase = blockIdx.x * 128;

    float acc[2][4][4];
    #pragma unroll
    for (int mi = 0; mi < 2; mi++)
        #pragma unroll
        for (int ni = 0; ni < 4; ni++)
            #pragma unroll
            for (int r = 0; r < 4; r++) acc[mi][ni][r] = 0.0f;

    for (int k0 = 0; k0 < K; k0 += 32) {
        float4 aReg[2], bReg[2];
        #pragma unroll
        for (int i = 0; i < 2; i++) {
            int fourIdx = tid + 512 * i;
            int r = fourIdx >> 3;
            int kq = fourIdx & 7;
            int gr = rowBase + r;
            float4 v = make_float4(0.f, 0.f, 0.f, 0.f);
            if (gr < Nrows) v = *(const float4*)&A[(size_t)gr * K + k0 + kq * 4];
            aReg[i].x = to_tf32(v.x); aReg[i].y = to_tf32(v.y);
            aReg[i].z = to_tf32(v.z); aReg[i].w = to_tf32(v.w);

            int gbr = colBase + r;
            float4 w = make_float4(0.f, 0.f, 0.f, 0.f);
            if (gbr < M) w = *(const float4*)&W[(size_t)gbr * K + k0 + kq * 4];
            bReg[i].x = to_tf32(w.x); bReg[i].y = to_tf32(w.y);
            bReg[i].z = to_tf32(w.z); bReg[i].w = to_tf32(w.w);
        }

        __syncthreads();
        #pragma unroll
        for (int i = 0; i < 2; i++) {
            int fourIdx = tid + 512 * i;
            int r = fourIdx >> 3;
            int kq = fourIdx & 7;
            *(float4*)&As[r][kq * 4] = aReg[i];
            *(float4*)&Bs[r][kq * 4] = bReg[i];
        }
        __syncthreads();

        #pragma unroll
        for (int ks = 0; ks < 4; ks++) {
            int kk = ks * 8;
            unsigned a[2][4], b[4][2];
            #pragma unroll
            for (int mi = 0; mi < 2; mi++) {
                int r0 = warpM * 32 + mi * 16 + quad;
                a[mi][0] = __float_as_uint(As[r0    ][kk + tq]);
                a[mi][1] = __float_as_uint(As[r0 + 8][kk + tq]);
                a[mi][2] = __float_as_uint(As[r0    ][kk + tq + 4]);
                a[mi][3] = __float_as_uint(As[r0 + 8][kk + tq + 4]);
            }
            #pragma unroll
            for (int ni = 0; ni < 4; ni++) {
                int c0 = warpN * 32 + ni * 8 + quad;
                b[ni][0] = __float_as_uint(Bs[c0][kk + tq]);
                b[ni][1] = __float_as_uint(Bs[c0][kk + tq + 4]);
            }
            #pragma unroll
            for (int mi = 0; mi < 2; mi++)
                #pragma unroll
                for (int ni = 0; ni < 4; ni++) {
                    asm volatile(
                        "mma.sync.aligned.m16n8k8.row.col.f32.tf32.tf32.f32 "
                        "{%0,%1,%2,%3},{%4,%5,%6,%7},{%8,%9},{%0,%1,%2,%3};"
                        : "+f"(acc[mi][ni][0]), "+f"(acc[mi][ni][1]),
                          "+f"(acc[mi][ni][2]), "+f"(acc[mi][ni][3])
                        : "r"(a[mi][0]), "r"(a[mi][1]), "r"(a[mi][2]), "r"(a[mi][3]),
                          "r"(b[ni][0]), "r"(b[ni][1]));
                }
        }
        __syncthreads();
    }

    #pragma unroll
    for (int mi = 0; mi < 2; mi++) {
        #pragma unroll
        for (int half = 0; half < 2; half++) {
            int r = rowBase + warpM * 32 + mi * 16 + quad + half * 8;
            if (r >= Nrows) continue;
            #pragma unroll
            for (int ni = 0; ni < 4; ni++) {
                int c = colBase + warpN * 32 + ni * 8 + 2 * tq;
                if (c >= M) continue;
                float2 v;
                v.x = acc[mi][ni][half * 2 + 0];
                v.y = acc[mi][ni][half * 2 + 1];
                *(float2*)&C[(size_t)r * M + c] = v;
            }
        }
    }
}

// ---------------------------------------------------------------------------
// GATv2 aggregation, warp per (node, 128-feature chunk), 4-edge unroll,
// no running max (logits O(10), fp32 exp headroom 85), dual accumulators.
// ---------------------------------------------------------------------------
__device__ __forceinline__ float dot_lrelu(float4 v, float4 xrr, float4 attr) {
    float zx = v.x + xrr.x; zx = zx > 0.f ? zx : 0.2f * zx;
    float zy = v.y + xrr.y; zy = zy > 0.f ? zy : 0.2f * zy;
    float zz = v.z + xrr.z; zz = zz > 0.f ? zz : 0.2f * zz;
    float zw = v.w + xrr.w; zw = zw > 0.f ? zw : 0.2f * zw;
    return attr.x * zx + attr.y * zy + attr.z * zz + attr.w * zw;
}

template <int F>
__global__ __launch_bounds__(256) void gat_agg_chunk_kernel(
    const float* __restrict__ xl, const float* __restrict__ xr,
    const int* __restrict__ rowptr, const int* __restrict__ colidx,
    const float* __restrict__ att, const float* __restrict__ bias,
    float* __restrict__ out) {
    constexpr int rowF4 = F / 4;
    int node = (blockIdx.x * blockDim.x + threadIdx.x) >> 5;
    int lane = threadIdx.x & 31;
    if (node >= NN) return;
    int fi = blockIdx.y * 32 + lane;

    const float4* xl4 = (const float4*)xl;
    float4 xrr  = ((const float4*)xr)[(size_t)node * rowF4 + fi];
    float4 attr = ((const float4*)att)[fi];

    float psumA = 0.f, psumB = 0.f;
    float4 accA = make_float4(0.f, 0.f, 0.f, 0.f);
    float4 accB = make_float4(0.f, 0.f, 0.f, 0.f);

    int beg = rowptr[node], end = rowptr[node + 1];
    int j = beg;
    for (; j + 4 <= end; j += 4) {
        int s0 = colidx[j], s1 = colidx[j + 1], s2 = colidx[j + 2], s3 = colidx[j + 3];
        float4 v0 = __ldg(&xl4[(size_t)s0 * rowF4 + fi]);
        float4 v1 = __ldg(&xl4[(size_t)s1 * rowF4 + fi]);
        float4 v2 = __ldg(&xl4[(size_t)s2 * rowF4 + fi]);
        float4 v3 = __ldg(&xl4[(size_t)s3 * rowF4 + fi]);
        float p0 = dot_lrelu(v0, xrr, attr);
        float p1 = dot_lrelu(v1, xrr, attr);
        float p2 = dot_lrelu(v2, xrr, attr);
        float p3 = dot_lrelu(v3, xrr, attr);
        #pragma unroll
        for (int o = 1; o < 16; o <<= 1) {
            p0 += __shfl_xor_sync(0xffffffffu, p0, o);
            p1 += __shfl_xor_sync(0xffffffffu, p1, o);
            p2 += __shfl_xor_sync(0xffffffffu, p2, o);
            p3 += __shfl_xor_sync(0xffffffffu, p3, o);
        }
        float e0 = __expf(p0), e1 = __expf(p1), e2 = __expf(p2), e3 = __expf(p3);
        psumA += e0 + e1;
        psumB += e2 + e3;
        accA.x += e0 * v0.x + e1 * v1.x;  accB.x += e2 * v2.x + e3 * v3.x;
        accA.y += e0 * v0.y + e1 * v1.y;  accB.y += e2 * v2.y + e3 * v3.y;
        accA.z += e0 * v0.z + e1 * v1.z;  accB.z += e2 * v2.z + e3 * v3.z;
        accA.w += e0 * v0.w + e1 * v1.w;  accB.w += e2 * v2.w + e3 * v3.w;
    }
    for (; j < end; j++) {
        int s0 = colidx[j];
        float4 v0 = __ldg(&xl4[(size_t)s0 * rowF4 + fi]);
        float p0 = dot_lrelu(v0, xrr, attr);
        #pragma unroll
        for (int o = 1; o < 16; o <<= 1)
            p0 += __shfl_xor_sync(0xffffffffu, p0, o);
        float e0 = __expf(p0);
        psumA += e0;
        accA.x += e0 * v0.x; accA.y += e0 * v0.y;
        accA.z += e0 * v0.z; accA.w += e0 * v0.w;
    }

    float4 bi = ((const float4*)bias)[fi];
    float inv = 1.0f / (psumA + psumB + 1e-16f);
    float4 v;
    v.x = (accA.x + accB.x) * inv + bi.x;
    v.y = (accA.y + accB.y) * inv + bi.y;
    v.z = (accA.z + accB.z) * inv + bi.z;
    v.w = (accA.w + accB.w) * inv + bi.w;
    v.x = v.x > 0.f ? v.x : 0.01f * v.x;
    v.y = v.y > 0.f ? v.y : 0.01f * v.y;
    v.z = v.z > 0.f ? v.z : 0.01f * v.z;
    v.w = v.w > 0.f ? v.w : 0.01f * v.w;
    ((float4*)out)[(size_t)node * rowF4 + fi] = v;
}

// H = 1 (F = 64): float2 per lane, full-warp reduce, 4-edge unroll, no max.
__global__ __launch_bounds__(256) void gat_agg1_kernel(
    const float* __restrict__ xl, const float* __restrict__ xr,
    const int* __restrict__ rowptr, const int* __restrict__ colidx,
    const float* __restrict__ att, const float* __restrict__ bias,
    float* __restrict__ out) {
    int node = (blockIdx.x * blockDim.x + threadIdx.x) >> 5;
    int lane = threadIdx.x & 31;
    if (node >= NN) return;

    const float2* xl2 = (const float2*)xl;
    float2 xrr = ((const float2*)xr)[(size_t)node * 32 + lane];
    float2 attr = ((const float2*)att)[lane];

    float psumA = 0.f, psumB = 0.f;
    float2 accA = make_float2(0.f, 0.f), accB = make_float2(0.f, 0.f);

    auto dot2 = [&](float2 v) {
        float zx = v.x + xrr.x; zx = zx > 0.f ? zx : 0.2f * zx;
        float zy = v.y + xrr.y; zy = zy > 0.f ? zy : 0.2f * zy;
        return attr.x * zx + attr.y * zy;
    };

    int beg = rowptr[node], end = rowptr[node + 1];
    int j = beg;
    for (; j + 4 <= end; j += 4) {
        int s0 = colidx[j], s1 = colidx[j + 1], s2 = colidx[j + 2], s3 = colidx[j + 3];
        float2 v0 = __ldg(&xl2[(size_t)s0 * 32 + lane]);
        float2 v1 = __ldg(&xl2[(size_t)s1 * 32 + lane]);
        float2 v2 = __ldg(&xl2[(size_t)s2 * 32 + lane]);
        float2 v3 = __ldg(&xl2[(size_t)s3 * 32 + lane]);
        float p0 = dot2(v0), p1 = dot2(v1), p2 = dot2(v2), p3 = dot2(v3);
        #pragma unroll
        for (int o = 1; o < 32; o <<= 1) {
            p0 += __shfl_xor_sync(0xffffffffu, p0, o);
            p1 += __shfl_xor_sync(0xffffffffu, p1, o);
            p2 += __shfl_xor_sync(0xffffffffu, p2, o);
            p3 += __shfl_xor_sync(0xffffffffu, p3, o);
        }
        float e0 = __expf(p0), e1 = __expf(p1), e2 = __expf(p2), e3 = __expf(p3);
        psumA += e0 + e1;
        psumB += e2 + e3;
        accA.x += e0 * v0.x + e1 * v1.x;  accB.x += e2 * v2.x + e3 * v3.x;
        accA.y += e0 * v0.y + e1 * v1.y;  accB.y += e2 * v2.y + e3 * v3.y;
    }
    for (; j < end; j++) {
        int s0 = colidx[j];
        float2 v0 = __ldg(&xl2[(size_t)s0 * 32 + lane]);
        float p0 = dot2(v0);
        #pragma unroll
        for (int o = 1; o < 32; o <<= 1)
            p0 += __shfl_xor_sync(0xffffffffu, p0, o);
        float e0 = __expf(p0);
        psumA += e0;
        accA.x += e0 * v0.x; accA.y += e0 * v0.y;
    }

    float2 bi = ((const float2*)bias)[lane];
    float inv = 1.0f / (psumA + psumB + 1e-16f);
    float2 v;
    v.x = (accA.x + accB.x) * inv + bi.x;
    v.y = (accA.y + accB.y) * inv + bi.y;
    v.x = v.x > 0.f ? v.x : 0.01f * v.x;
    v.y = v.y > 0.f ? v.y : 0.01f * v.y;
    ((float2*)out)[(size_t)node * 32 + lane] = v;
}

// ---------------------------------------------------------------------------
// Fused pooling + head (batch_index sorted -> binary-searched ranges)
// ---------------------------------------------------------------------------
__global__ __launch_bounds__(256) void pool_head_kernel(
    const float* __restrict__ h, const int* __restrict__ batch,
    const float* __restrict__ out_w, const float* __restrict__ out_b,
    float* __restrict__ d_out) {
    int g = blockIdx.x;
    int t = threadIdx.x;
    int f = t & 63, slice = t >> 6;

    __shared__ int bounds[2];
    __shared__ float smax[4][64], ssum[4][64];
    __shared__ float hid[128];

    if (t < 2) {
        int key = g + t;
        int lo = 0, hi = NN;
        while (lo < hi) {
            int mid = (lo + hi) >> 1;
            if (batch[mid] < key) lo = mid + 1; else hi = mid;
        }
        bounds[t] = lo;
    }
    __syncthreads();
    int start = bounds[0], end = bounds[1];

    float mx = -INFINITY, sm = 0.0f;
    for (int n = start + slice; n < end; n += 4) {
        float v = h[(size_t)n * 64 + f];
        mx = fmaxf(mx, v);
        sm += v;
    }
    smax[slice][f] = mx;
    ssum[slice][f] = sm;
    __syncthreads();

    if (t < 64) {
        float m = fmaxf(fmaxf(smax[0][t], smax[1][t]), fmaxf(smax[2][t], smax[3][t]));
        float s = ssum[0][t] + ssum[1][t] + ssum[2][t] + ssum[3][t];
        int cnt = end - start;
        float inv = 1.0f / (float)(cnt > 1 ? cnt : 1);
        hid[t] = m;
        hid[64 + t] = s * inv;
    }
    __syncthreads();

    if (t < 128) d_out[512 + (size_t)g * 128 + t] = hid[t];
    if (t < 2) {
        float s = out_b[t];
        #pragma unroll 8
        for (int k = 0; k < 128; k++) s = fmaf(hid[k], out_w[t * 128 + k], s);
        d_out[g * 2 + t] = s;
    }
}

// ---------------------------------------------------------------------------
// Launch
// ---------------------------------------------------------------------------
extern "C" void kernel_launch(void* const* d_in, const int* in_sizes, int n_in,
                              void* d_out, int out_size) {
    const float* x        = (const float*)d_in[0];
    const int*   edge_idx = (const int*)d_in[1];
    const int*   batch    = (const int*)d_in[2];
    const float* w1_l = (const float*)d_in[3];
    const float* w1_r = (const float*)d_in[4];
    const float* att1 = (const float*)d_in[5];
    const float* b1   = (const float*)d_in[6];
    const float* w2_l = (const float*)d_in[7];
    const float* w2_r = (const float*)d_in[8];
    const float* att2 = (const float*)d_in[9];
    const float* b2   = (const float*)d_in[10];
    const float* w3_l = (const float*)d_in[11];
    const float* w3_r = (const float*)d_in[12];
    const float* att3 = (const float*)d_in[13];
    const float* b3   = (const float*)d_in[14];
    const float* out_w = (const float*)d_in[15];
    const float* out_b = (const float*)d_in[16];
    float* out = (float*)d_out;

    void* p;
    float *xl, *xr, *h; int *deg, *row, *fill, *col, *bsum;
    cudaGetSymbolAddress(&p, g_xl);   xl   = (float*)p;
    cudaGetSymbolAddress(&p, g_xr);   xr   = (float*)p;
    cudaGetSymbolAddress(&p, g_h);    h    = (float*)p;
    cudaGetSymbolAddress(&p, g_deg);  deg  = (int*)p;
    cudaGetSymbolAddress(&p, g_row);  row  = (int*)p;
    cudaGetSymbolAddress(&p, g_fill); fill = (int*)p;
    cudaGetSymbolAddress(&p, g_col);  col  = (int*)p;
    cudaGetSymbolAddress(&p, g_bsum); bsum = (int*)p;

    // --- CSR build ---
    init_kernel<<<(NN / 4 + 255) / 256, 256>>>((int4*)deg);
    hist_kernel<<<(EE / 4 + 255) / 256, 256>>>(edge_idx, deg);
    scan_partial<<<SCAN_NB, SCAN_BLK>>>(deg, row, bsum);
    scan_apply<<<SCAN_NB, SCAN_BLK>>>(deg, row, fill, bsum, col);
    scatter_kernel<<<(EE / 4 + 255) / 256, 256>>>(edge_idx, fill, col);

    const int AGG_BLOCKS = (NN * 32 + 255) / 256;
    const int NB = (NN + 127) / 128;

    // --- Layer 1: 128 -> 256 (H=4, 2 chunks) ---
    tf32_gemm2<<<dim3(2, NB, 2), 512>>>(x, w1_l, w1_r, xl, xr, NN, 128, 256);
    gat_agg_chunk_kernel<256><<<dim3(AGG_BLOCKS, 2), 256>>>(xl, xr, row, col, att1, b1, h);

    // --- Layer 2: 256 -> 128 (H=2, 1 chunk) ---
    tf32_gemm2<<<dim3(1, NB, 2), 512>>>(h, w2_l, w2_r, xl, xr, NN, 256, 128);
    gat_agg_chunk_kernel<128><<<dim3(AGG_BLOCKS, 1), 256>>>(xl, xr, row, col, att2, b2, h);

    // --- Layer 3: 128 -> 64 (H=1) ---
    tf32_gemm2<<<dim3(1, NB, 2), 512>>>(h, w3_l, w3_r, xl, xr, NN, 128, 64);
    gat_agg1_kernel<<<AGG_BLOCKS, 256>>>(xl, xr, row, col, att3, b3, h);

    // --- Fused pooling + head ---
    pool_head_kernel<<<GG, 256>>>(h, batch, out_w, out_b, out);
}